// round 8
// baseline (speedup 1.0000x reference)
#include <cuda_runtime.h>

#define NB    64
#define NV    4096
#define NFEAT 16
#define NA    8
#define NP    16
#define NOUT  16
#define S1    16                 // blocks per batch
#define CH    256                // vertices per block
#define GRID1 (NB * S1)          // 1024

typedef unsigned long long u64;

__device__ __forceinline__ u64 pk(float lo, float hi) {
    u64 r; asm("mov.b64 %0, {%1, %2};" : "=l"(r) : "f"(lo), "f"(hi)); return r;
}
__device__ __forceinline__ void upk(u64 v, float& lo, float& hi) {
    asm("mov.b64 {%0, %1}, %2;" : "=f"(lo), "=f"(hi) : "l"(v));
}
__device__ __forceinline__ u64 fma2(u64 a, u64 b, u64 c) {
    u64 d; asm("fma.rn.f32x2 %0, %1, %2, %3;" : "=l"(d) : "l"(a), "l"(b), "l"(c)); return d;
}
__device__ __forceinline__ u64 add2(u64 a, u64 b) {
    u64 d; asm("add.rn.f32x2 %0, %1, %2;" : "=l"(d) : "l"(a), "l"(b)); return d;
}
__device__ __forceinline__ u64 mul2(u64 a, u64 b) {
    u64 d; asm("mul.rn.f32x2 %0, %1, %2;" : "=l"(d) : "l"(a), "l"(b)); return d;
}

// Per-(b,split) partials; slot owned exclusively -> no zeroing kernel.
__device__ float    g_part[GRID1 * 128];
// Per-batch M[a][n], produced by each batch's last-arriving k1 block.
__device__ float    g_M[NB * 128];
// Monotonic per-batch arrival counters (replay-safe: act on (old&15)==15).
__device__ unsigned g_cnt[NB];

// ---------------------------------------------------------------------------
// k1: partial aggregation (packed f32x2 matvecs) + per-batch fan-in -> g_M.
// ---------------------------------------------------------------------------
__global__ __launch_bounds__(256, 3) void k_aggregate(
    const float* __restrict__ data, const int* __restrict__ num_vertex,
    const float* __restrict__ W_flr, const float* __restrict__ b_flr,
    const float* __restrict__ W_s,   const float* __restrict__ b_s,
    const float* __restrict__ W_out)
{
    __shared__ float4 sWf4[NFEAT][4];     // pair-ordered; read as u64*
    __shared__ float4 sWs4[NFEAT][2];
    __shared__ float  sbf[NP];
    __shared__ float  sbs[NA];
    __shared__ u64    sFeatT[8 * CH];     // [j][v]: feat pair j of vertex v
    __shared__ u64    sEwT[8 * CH];       // [a][v]: (ew, ew) duplicated pair
    __shared__ float  sFan[128];
    __shared__ unsigned sLast;

    const int t     = threadIdx.x;
    const int b     = blockIdx.x / S1;
    const int split = blockIdx.x % S1;
    const int nv    = num_vertex[b];
    const int vbase = split * CH;
    const bool work = (vbase < nv);       // block-uniform

    if (work) {
        if (t < 64) {
            sWf4[t >> 2][t & 3] = ((const float4*)W_flr)[t];
        } else if (t < 96) {
            const int u = t - 64;
            sWs4[u >> 1][u & 1] = ((const float4*)W_s)[u];
        } else if (t < 112) {
            sbf[t - 96] = b_flr[t - 96];
        } else if (t < 120) {
            sbs[t - 112] = b_s[t - 112];
        }
        __syncthreads();

        const int v = vbase + t;
        if (v < nv) {
            const float4* dp = (const float4*)(data + ((size_t)(b * NV + v)) * NFEAT);
            const float4 x0 = dp[0], x1 = dp[1], x2 = dp[2], x3 = dp[3];
            float x[16];
            x[0]=x0.x;  x[1]=x0.y;  x[2]=x0.z;  x[3]=x0.w;
            x[4]=x1.x;  x[5]=x1.y;  x[6]=x1.z;  x[7]=x1.w;
            x[8]=x2.x;  x[9]=x2.y;  x[10]=x2.z; x[11]=x2.w;
            x[12]=x3.x; x[13]=x3.y; x[14]=x3.z; x[15]=x3.w;

            u64 aF[8], aD[4];
            #pragma unroll
            for (int j = 0; j < 8; ++j) aF[j] = pk(sbf[2*j], sbf[2*j+1]);
            #pragma unroll
            for (int j = 0; j < 4; ++j) aD[j] = pk(sbs[2*j], sbs[2*j+1]);

            #pragma unroll
            for (int f = 0; f < 16; ++f) {
                const u64 xx = pk(x[f], x[f]);
                const u64* wf = (const u64*)&sWf4[f][0];
                #pragma unroll
                for (int j = 0; j < 8; ++j) aF[j] = fma2(xx, wf[j], aF[j]);
                const u64* ws = (const u64*)&sWs4[f][0];
                #pragma unroll
                for (int j = 0; j < 4; ++j) aD[j] = fma2(xx, ws[j], aD[j]);
            }

            #pragma unroll
            for (int j = 0; j < 8; ++j) sFeatT[j * CH + t] = aF[j];
            #pragma unroll
            for (int j = 0; j < 4; ++j) {
                float d0, d1; upk(aD[j], d0, d1);
                const float e0 = __expf(-d0*d0);
                const float e1 = __expf(-d1*d1);
                sEwT[(2*j)   * CH + t] = pk(e0, e0);
                sEwT[(2*j+1) * CH + t] = pk(e1, e1);
            }
        } else {
            #pragma unroll
            for (int j = 0; j < 8; ++j) sFeatT[j * CH + t] = 0ull;
            #pragma unroll
            for (int j = 0; j < 8; ++j) sEwT[j * CH + t]   = 0ull;
        }
        __syncthreads();

        // reduce: 32 owners (aa=o>>2, pg=o&3) x 8 slices of 32 vertices.
        const int owner = t & 31;
        const int aa    = owner >> 2;
        const int pg    = owner & 3;
        const int slice = t >> 5;
        u64 ac0 = 0ull, ac1 = 0ull;
        const int v0 = slice * 32;
        if (vbase + v0 < nv) {               // warp-uniform skip of dead slices
            #pragma unroll 8
            for (int i = 0; i < 32; ++i) {
                const int vv = v0 + i;
                const u64 ww = sEwT[aa * CH + vv];
                ac0 = fma2(ww, sFeatT[(pg*2)   * CH + vv], ac0);
                ac1 = fma2(ww, sFeatT[(pg*2+1) * CH + vv], ac1);
            }
        }
        __syncthreads();

        // cross-slice reduction (reuse sFeatT as u64 red[8][32][2])
        u64* sRed = sFeatT;
        sRed[(slice * 32 + owner) * 2 + 0] = ac0;
        sRed[(slice * 32 + owner) * 2 + 1] = ac1;
        __syncthreads();
        if (t < 32) {
            u64 s0 = sRed[t*2], s1 = sRed[t*2 + 1];
            #pragma unroll
            for (int sl = 1; sl < 8; ++sl) {
                s0 = add2(s0, sRed[(sl * 32 + t) * 2 + 0]);
                s1 = add2(s1, sRed[(sl * 32 + t) * 2 + 1]);
            }
            // owner t covers elements 4t..4t+3 -> u64 slots 2t, 2t+1
            ((u64*)g_part)[blockIdx.x * 64 + t*2 + 0] = s0;
            ((u64*)g_part)[blockIdx.x * 64 + t*2 + 1] = s1;
            __threadfence();                 // release partial
        }
    } else {
        if (t < 32) {
            ((u64*)g_part)[blockIdx.x * 64 + t*2 + 0] = 0ull;
            ((u64*)g_part)[blockIdx.x * 64 + t*2 + 1] = 0ull;
            __threadfence();
        }
    }
    __syncthreads();

    // ---- per-batch fan-in: last arrival reduces partials, computes M ----
    if (t == 0) {
        const unsigned old = atomicAdd(&g_cnt[b], 1u);
        sLast = ((old & (S1 - 1)) == (S1 - 1)) ? 1u : 0u;
    }
    __syncthreads();
    if (sLast) {
        __threadfence();                     // acquire siblings' partials
        if (t < 32) {
            float4 s = make_float4(0.f, 0.f, 0.f, 0.f);
            #pragma unroll
            for (int sp = 0; sp < S1; ++sp) {
                const float4 r = ((const float4*)g_part)[(b * S1 + sp) * 32 + t];
                s.x += r.x; s.y += r.y; s.z += r.z; s.w += r.w;
            }
            const float inv = 1.0f / (float)NV;
            s.x *= inv; s.y *= inv; s.z *= inv; s.w *= inv;
            ((float4*)sFan)[t] = s;          // agg[a*16+p]
        }
        __syncthreads();
        if (t < 128) {
            const int a = t >> 4, n = t & 15;
            float m = 0.f;
            #pragma unroll
            for (int p = 0; p < NP; ++p)
                m += sFan[a*NP + p] * W_out[(a*NP + p)*NOUT + n];
            g_M[b * 128 + t] = m;            // visible to k2 via launch edge
        }
    }
}

// ---------------------------------------------------------------------------
// k2: out[b,v,:] = mask * (sum_a ew[v,a] * M[b,a,:] + b_out). No prologue
//     reduction: g_M is ready. Packed f32x2 matvec + epilogue.
// ---------------------------------------------------------------------------
__global__ __launch_bounds__(256, 4) void k_output(
    const float* __restrict__ data, const int* __restrict__ num_vertex,
    const float* __restrict__ W_s, const float* __restrict__ b_s,
    const float* __restrict__ b_out, float* __restrict__ out)
{
    __shared__ float4 sWs4[NFEAT][2];
    __shared__ __align__(16) float sM[128];
    __shared__ float sbs[NA];
    __shared__ float sbo[NOUT];

    const int t  = threadIdx.x;
    const int b  = blockIdx.x / S1;
    const int vb = (blockIdx.x % S1) * CH;
    const int nv = num_vertex[b];
    const int v  = vb + t;
    float4* op = (float4*)(out + ((size_t)(b * NV + v)) * NOUT);
    const float4 z = make_float4(0.f, 0.f, 0.f, 0.f);

    if (vb >= nv) {                          // fully masked block
        op[0] = z; op[1] = z; op[2] = z; op[3] = z;
        return;
    }

    if (t < 32) {
        ((float4*)sM)[t] = ((const float4*)g_M)[b * 32 + t];
    } else if (t < 64) {
        const int u = t - 32;
        sWs4[u >> 1][u & 1] = ((const float4*)W_s)[u];
    } else if (t < 72) {
        sbs[t - 64] = b_s[t - 64];
    } else if (t < 88) {
        sbo[t - 72] = b_out[t - 72];
    }
    __syncthreads();

    if (v < nv) {
        const float4* dp = (const float4*)(data + ((size_t)(b * NV + v)) * NFEAT);
        const float4 x0 = dp[0], x1 = dp[1], x2 = dp[2], x3 = dp[3];
        float x[16];
        x[0]=x0.x;  x[1]=x0.y;  x[2]=x0.z;  x[3]=x0.w;
        x[4]=x1.x;  x[5]=x1.y;  x[6]=x1.z;  x[7]=x1.w;
        x[8]=x2.x;  x[9]=x2.y;  x[10]=x2.z; x[11]=x2.w;
        x[12]=x3.x; x[13]=x3.y; x[14]=x3.z; x[15]=x3.w;

        u64 aD[4];
        #pragma unroll
        for (int j = 0; j < 4; ++j) aD[j] = pk(sbs[2*j], sbs[2*j+1]);
        #pragma unroll
        for (int f = 0; f < 16; ++f) {
            const u64 xx = pk(x[f], x[f]);
            const u64* ws = (const u64*)&sWs4[f][0];
            #pragma unroll
            for (int j = 0; j < 4; ++j) aD[j] = fma2(xx, ws[j], aD[j]);
        }
        float ew[8];
        #pragma unroll
        for (int j = 0; j < 4; ++j) {
            float d0, d1; upk(aD[j], d0, d1);
            ew[2*j]   = __expf(-d0*d0);
            ew[2*j+1] = __expf(-d1*d1);
        }

        u64 o[8];
        #pragma unroll
        for (int j = 0; j < 8; ++j) o[j] = pk(sbo[2*j], sbo[2*j+1]);
        const u64* m = (const u64*)sM;
        #pragma unroll
        for (int a = 0; a < NA; ++a) {
            const u64 ww = pk(ew[a], ew[a]);
            const u64* mr = m + a * 8;
            #pragma unroll
            for (int j = 0; j < 8; ++j) o[j] = fma2(ww, mr[j], o[j]);
        }
        #pragma unroll
        for (int k = 0; k < 4; ++k) {
            float a0, a1, a2, a3;
            upk(o[2*k],   a0, a1);
            upk(o[2*k+1], a2, a3);
            op[k] = make_float4(a0, a1, a2, a3);
        }
    } else {
        op[0] = z; op[1] = z; op[2] = z; op[3] = z;
    }
}

extern "C" void kernel_launch(void* const* d_in, const int* in_sizes, int n_in,
                              void* d_out, int out_size) {
    const float* data       = (const float*)d_in[0];
    const int*   num_vertex = (const int*)  d_in[1];
    const float* W_flr      = (const float*)d_in[2];
    const float* b_flr      = (const float*)d_in[3];
    const float* W_s        = (const float*)d_in[4];
    const float* b_s        = (const float*)d_in[5];
    const float* W_out      = (const float*)d_in[6];
    const float* b_out      = (const float*)d_in[7];
    float* out = (float*)d_out;

    k_aggregate<<<GRID1, 256>>>(data, num_vertex, W_flr, b_flr, W_s, b_s, W_out);
    k_output<<<GRID1, 256>>>(data, num_vertex, W_s, b_s, b_out, out);
}

// round 9
// speedup vs baseline: 1.2064x; 1.2064x over previous
#include <cuda_runtime.h>

#define NB    64
#define NV    4096
#define NFEAT 16
#define NA    8
#define NP    16
#define NOUT  16
#define S1    8                  // blocks per batch
#define CHB   512                // vertices per block (2 per thread)
#define GRID1 (NB * S1)          // 512

// Per-(b,split) partials; slot owned exclusively -> no zeroing kernel.
__device__ float    g_part[GRID1 * 128];
// Per-batch M[a][n], produced by each batch's last-arriving k1 block.
__device__ float    g_M[NB * 128];
// Monotonic per-batch arrival counters (replay-safe: act on (old&7)==7).
__device__ unsigned g_cnt[NB];

// ---------------------------------------------------------------------------
// k1: partial aggregation, 512 vertices/block, + per-batch fan-in -> g_M.
// ---------------------------------------------------------------------------
__global__ __launch_bounds__(256, 3) void k_aggregate(
    const float* __restrict__ data, const int* __restrict__ num_vertex,
    const float* __restrict__ W_flr, const float* __restrict__ b_flr,
    const float* __restrict__ W_s,   const float* __restrict__ b_s,
    const float* __restrict__ W_out)
{
    __shared__ float4 sWf4[NFEAT][4];
    __shared__ float4 sWs4[NFEAT][2];
    __shared__ float  sbf[NP];
    __shared__ float  sbs[NA];
    __shared__ float4 sStage[CHB * 6];    // [0..3]=feat, [4..5]=ew per vertex; 48KB
    __shared__ float  sFan[128];
    __shared__ unsigned sLast;

    const int t     = threadIdx.x;
    const int b     = blockIdx.x / S1;
    const int split = blockIdx.x % S1;
    const int nv    = num_vertex[b];
    const int vbase = split * CHB;
    const bool work = (vbase < nv);       // block-uniform
    const float4 z  = make_float4(0.f, 0.f, 0.f, 0.f);

    if (work) {
        if (t < 64) {
            sWf4[t >> 2][t & 3] = ((const float4*)W_flr)[t];
        } else if (t < 96) {
            const int u = t - 64;
            sWs4[u >> 1][u & 1] = ((const float4*)W_s)[u];
        } else if (t < 112) {
            sbf[t - 96] = b_flr[t - 96];
        } else if (t < 120) {
            sbs[t - 112] = b_s[t - 112];
        }
        __syncthreads();

        // hoist both vertices' data loads (8 LDG.128 in flight)
        const int v0 = vbase + t;
        const int v1 = vbase + 256 + t;
        const bool val0 = (v0 < nv), val1 = (v1 < nv);
        float4 a0 = z, a1 = z, a2 = z, a3 = z;
        float4 c0 = z, c1 = z, c2 = z, c3 = z;
        if (val0) {
            const float4* dp = (const float4*)(data + ((size_t)(b * NV + v0)) * NFEAT);
            a0 = dp[0]; a1 = dp[1]; a2 = dp[2]; a3 = dp[3];
        }
        if (val1) {
            const float4* dp = (const float4*)(data + ((size_t)(b * NV + v1)) * NFEAT);
            c0 = dp[0]; c1 = dp[1]; c2 = dp[2]; c3 = dp[3];
        }

        #pragma unroll
        for (int u = 0; u < 2; ++u) {
            const int row = u * 256 + t;
            const bool val = u ? val1 : val0;
            if (val) {
                float x[16];
                if (u == 0) {
                    x[0]=a0.x;  x[1]=a0.y;  x[2]=a0.z;  x[3]=a0.w;
                    x[4]=a1.x;  x[5]=a1.y;  x[6]=a1.z;  x[7]=a1.w;
                    x[8]=a2.x;  x[9]=a2.y;  x[10]=a2.z; x[11]=a2.w;
                    x[12]=a3.x; x[13]=a3.y; x[14]=a3.z; x[15]=a3.w;
                } else {
                    x[0]=c0.x;  x[1]=c0.y;  x[2]=c0.z;  x[3]=c0.w;
                    x[4]=c1.x;  x[5]=c1.y;  x[6]=c1.z;  x[7]=c1.w;
                    x[8]=c2.x;  x[9]=c2.y;  x[10]=c2.z; x[11]=c2.w;
                    x[12]=c3.x; x[13]=c3.y; x[14]=c3.z; x[15]=c3.w;
                }
                #pragma unroll
                for (int g = 0; g < 4; ++g) {
                    float s0 = sbf[g*4+0], s1 = sbf[g*4+1];
                    float s2 = sbf[g*4+2], s3 = sbf[g*4+3];
                    #pragma unroll
                    for (int f = 0; f < 16; ++f) {
                        const float4 w = sWf4[f][g];
                        s0 += x[f]*w.x; s1 += x[f]*w.y;
                        s2 += x[f]*w.z; s3 += x[f]*w.w;
                    }
                    sStage[row*6 + g] = make_float4(s0, s1, s2, s3);
                }
                float s0 = sbs[0], s1 = sbs[1], s2 = sbs[2], s3 = sbs[3];
                float u0 = sbs[4], u1 = sbs[5], u2 = sbs[6], u3 = sbs[7];
                #pragma unroll
                for (int f = 0; f < 16; ++f) {
                    const float4 w0 = sWs4[f][0];
                    const float4 w1 = sWs4[f][1];
                    s0 += x[f]*w0.x; s1 += x[f]*w0.y;
                    s2 += x[f]*w0.z; s3 += x[f]*w0.w;
                    u0 += x[f]*w1.x; u1 += x[f]*w1.y;
                    u2 += x[f]*w1.z; u3 += x[f]*w1.w;
                }
                sStage[row*6 + 4] = make_float4(__expf(-s0*s0), __expf(-s1*s1),
                                                __expf(-s2*s2), __expf(-s3*s3));
                sStage[row*6 + 5] = make_float4(__expf(-u0*u0), __expf(-u1*u1),
                                                __expf(-u2*u2), __expf(-u3*u3));
            } else {
                #pragma unroll
                for (int g = 0; g < 6; ++g) sStage[row*6 + g] = z;
            }
        }
        __syncthreads();

        // reduce: 32 owners (aa=o>>2, pg=o&3) x 8 slices of 64 vertices.
        const int owner = t & 31;
        const int aa    = owner >> 2;
        const int pg    = owner & 3;
        const int slice = t >> 5;
        const float* sS = (const float*)sStage;
        float4 acc = z;
        const int r0 = slice * 64;
        if (vbase + r0 < nv) {               // warp-uniform skip of dead slices
            #pragma unroll 4
            for (int i = 0; i < 64; ++i) {
                const int vv = r0 + i;
                const float  w = sS[vv*24 + 16 + aa];   // broadcast (32B window)
                const float4 f = sStage[vv*6 + pg];     // multicast 64B
                acc.x += w * f.x; acc.y += w * f.y;
                acc.z += w * f.z; acc.w += w * f.w;
            }
        }
        __syncthreads();

        // cross-slice reduction (reuse sStage as sRed[8][32])
        float4* sRed = sStage;
        sRed[slice * 32 + owner] = acc;
        __syncthreads();
        if (t < 32) {
            float4 s = sRed[t];
            #pragma unroll
            for (int sl = 1; sl < 8; ++sl) {
                const float4 r = sRed[sl * 32 + t];
                s.x += r.x; s.y += r.y; s.z += r.z; s.w += r.w;
            }
            ((float4*)g_part)[blockIdx.x * 32 + t] = s;
            __threadfence();                 // release partial
        }
    } else {
        if (t < 32) {
            ((float4*)g_part)[blockIdx.x * 32 + t] = z;
            __threadfence();
        }
    }
    __syncthreads();

    // ---- per-batch fan-in: last arrival reduces partials, computes M ----
    if (t == 0) {
        const unsigned old = atomicAdd(&g_cnt[b], 1u);
        sLast = ((old & (S1 - 1)) == (S1 - 1)) ? 1u : 0u;
    }
    __syncthreads();
    if (sLast) {
        __threadfence();                     // acquire siblings' partials
        if (t < 32) {
            float4 s = z;
            #pragma unroll
            for (int sp = 0; sp < S1; ++sp) {
                const float4 r = ((const float4*)g_part)[(b * S1 + sp) * 32 + t];
                s.x += r.x; s.y += r.y; s.z += r.z; s.w += r.w;
            }
            const float inv = 1.0f / (float)NV;
            s.x *= inv; s.y *= inv; s.z *= inv; s.w *= inv;
            ((float4*)sFan)[t] = s;          // agg[a*16+p]
        }
        __syncthreads();
        if (t < 128) {
            const int a = t >> 4, n = t & 15;
            float m = 0.f;
            #pragma unroll
            for (int p = 0; p < NP; ++p)
                m += sFan[a*NP + p] * W_out[(a*NP + p)*NOUT + n];
            g_M[b * 128 + t] = m;            // visible to k2 via launch edge
        }
    }
}

// ---------------------------------------------------------------------------
// k2: out[b,v,:] = mask * (sum_a ew[v,a] * M[b,a,:] + b_out).
//     2 vertices/thread, no prologue reduction (g_M ready).
// ---------------------------------------------------------------------------
__global__ __launch_bounds__(256, 3) void k_output(
    const float* __restrict__ data, const int* __restrict__ num_vertex,
    const float* __restrict__ W_s, const float* __restrict__ b_s,
    const float* __restrict__ b_out, float* __restrict__ out)
{
    __shared__ float4 sWs4[NFEAT][2];
    __shared__ __align__(16) float sM[128];
    __shared__ float sbs[NA];
    __shared__ float sbo[NOUT];

    const int t  = threadIdx.x;
    const int b  = blockIdx.x / S1;
    const int vb = (blockIdx.x % S1) * CHB;
    const int nv = num_vertex[b];
    const float4 z = make_float4(0.f, 0.f, 0.f, 0.f);

    const int v0 = vb + t, v1 = vb + 256 + t;
    float4* op0 = (float4*)(out + ((size_t)(b * NV + v0)) * NOUT);
    float4* op1 = (float4*)(out + ((size_t)(b * NV + v1)) * NOUT);

    if (vb >= nv) {                          // fully masked block
        op0[0] = z; op0[1] = z; op0[2] = z; op0[3] = z;
        op1[0] = z; op1[1] = z; op1[2] = z; op1[3] = z;
        return;
    }

    // hoist both data loads to overlap smem prologue
    const bool val0 = (v0 < nv), val1 = (v1 < nv);
    float4 a0 = z, a1 = z, a2 = z, a3 = z;
    float4 c0 = z, c1 = z, c2 = z, c3 = z;
    if (val0) {
        const float4* dp = (const float4*)(data + ((size_t)(b * NV + v0)) * NFEAT);
        a0 = dp[0]; a1 = dp[1]; a2 = dp[2]; a3 = dp[3];
    }
    if (val1) {
        const float4* dp = (const float4*)(data + ((size_t)(b * NV + v1)) * NFEAT);
        c0 = dp[0]; c1 = dp[1]; c2 = dp[2]; c3 = dp[3];
    }

    if (t < 32) {
        ((float4*)sM)[t] = ((const float4*)g_M)[b * 32 + t];
    } else if (t < 64) {
        const int u = t - 32;
        sWs4[u >> 1][u & 1] = ((const float4*)W_s)[u];
    } else if (t < 72) {
        sbs[t - 64] = b_s[t - 64];
    } else if (t < 88) {
        sbo[t - 72] = b_out[t - 72];
    }
    __syncthreads();

    float ew0[8], ew1[8];
    {
        float x[16];
        x[0]=a0.x;  x[1]=a0.y;  x[2]=a0.z;  x[3]=a0.w;
        x[4]=a1.x;  x[5]=a1.y;  x[6]=a1.z;  x[7]=a1.w;
        x[8]=a2.x;  x[9]=a2.y;  x[10]=a2.z; x[11]=a2.w;
        x[12]=a3.x; x[13]=a3.y; x[14]=a3.z; x[15]=a3.w;
        float s0 = sbs[0], s1 = sbs[1], s2 = sbs[2], s3 = sbs[3];
        float u0 = sbs[4], u1 = sbs[5], u2 = sbs[6], u3 = sbs[7];
        #pragma unroll
        for (int f = 0; f < 16; ++f) {
            const float4 w0 = sWs4[f][0];
            const float4 w1 = sWs4[f][1];
            s0 += x[f]*w0.x; s1 += x[f]*w0.y; s2 += x[f]*w0.z; s3 += x[f]*w0.w;
            u0 += x[f]*w1.x; u1 += x[f]*w1.y; u2 += x[f]*w1.z; u3 += x[f]*w1.w;
        }
        ew0[0]=__expf(-s0*s0); ew0[1]=__expf(-s1*s1);
        ew0[2]=__expf(-s2*s2); ew0[3]=__expf(-s3*s3);
        ew0[4]=__expf(-u0*u0); ew0[5]=__expf(-u1*u1);
        ew0[6]=__expf(-u2*u2); ew0[7]=__expf(-u3*u3);
    }
    {
        float x[16];
        x[0]=c0.x;  x[1]=c0.y;  x[2]=c0.z;  x[3]=c0.w;
        x[4]=c1.x;  x[5]=c1.y;  x[6]=c1.z;  x[7]=c1.w;
        x[8]=c2.x;  x[9]=c2.y;  x[10]=c2.z; x[11]=c2.w;
        x[12]=c3.x; x[13]=c3.y; x[14]=c3.z; x[15]=c3.w;
        float s0 = sbs[0], s1 = sbs[1], s2 = sbs[2], s3 = sbs[3];
        float u0 = sbs[4], u1 = sbs[5], u2 = sbs[6], u3 = sbs[7];
        #pragma unroll
        for (int f = 0; f < 16; ++f) {
            const float4 w0 = sWs4[f][0];
            const float4 w1 = sWs4[f][1];
            s0 += x[f]*w0.x; s1 += x[f]*w0.y; s2 += x[f]*w0.z; s3 += x[f]*w0.w;
            u0 += x[f]*w1.x; u1 += x[f]*w1.y; u2 += x[f]*w1.z; u3 += x[f]*w1.w;
        }
        ew1[0]=__expf(-s0*s0); ew1[1]=__expf(-s1*s1);
        ew1[2]=__expf(-s2*s2); ew1[3]=__expf(-s3*s3);
        ew1[4]=__expf(-u0*u0); ew1[5]=__expf(-u1*u1);
        ew1[6]=__expf(-u2*u2); ew1[7]=__expf(-u3*u3);
    }

    float4 o0[4], o1[4];
    #pragma unroll
    for (int j = 0; j < 4; ++j) {
        o0[j] = make_float4(sbo[j*4], sbo[j*4+1], sbo[j*4+2], sbo[j*4+3]);
        o1[j] = o0[j];
    }
    #pragma unroll
    for (int a = 0; a < NA; ++a) {
        const float w0 = ew0[a], w1 = ew1[a];
        const float4* mrow = (const float4*)(sM + a * NOUT);
        #pragma unroll
        for (int j = 0; j < 4; ++j) {
            const float4 m = mrow[j];         // one LDS.128 serves both vertices
            o0[j].x += w0 * m.x; o0[j].y += w0 * m.y;
            o0[j].z += w0 * m.z; o0[j].w += w0 * m.w;
            o1[j].x += w1 * m.x; o1[j].y += w1 * m.y;
            o1[j].z += w1 * m.z; o1[j].w += w1 * m.w;
        }
    }

    if (val0) { op0[0]=o0[0]; op0[1]=o0[1]; op0[2]=o0[2]; op0[3]=o0[3]; }
    else      { op0[0]=z;     op0[1]=z;     op0[2]=z;     op0[3]=z;     }
    if (val1) { op1[0]=o1[0]; op1[1]=o1[1]; op1[2]=o1[2]; op1[3]=o1[3]; }
    else      { op1[0]=z;     op1[1]=z;     op1[2]=z;     op1[3]=z;     }
}

extern "C" void kernel_launch(void* const* d_in, const int* in_sizes, int n_in,
                              void* d_out, int out_size) {
    const float* data       = (const float*)d_in[0];
    const int*   num_vertex = (const int*)  d_in[1];
    const float* W_flr      = (const float*)d_in[2];
    const float* b_flr      = (const float*)d_in[3];
    const float* W_s        = (const float*)d_in[4];
    const float* b_s        = (const float*)d_in[5];
    const float* W_out      = (const float*)d_in[6];
    const float* b_out      = (const float*)d_in[7];
    float* out = (float*)d_out;

    k_aggregate<<<GRID1, 256>>>(data, num_vertex, W_flr, b_flr, W_s, b_s, W_out);
    k_output<<<GRID1, 256>>>(data, num_vertex, W_s, b_s, b_out, out);
}

// round 10
// speedup vs baseline: 1.3911x; 1.1532x over previous
#include <cuda_runtime.h>

#define NB    64
#define NV    4096
#define NFEAT 16
#define NA    8
#define NP    16
#define NOUT  16
#define S1    16                 // blocks per batch
#define CH    256                // vertices per block (1 per thread)
#define GRID1 (NB * S1)          // 1024

// Per-(b,split) partials; slot owned exclusively -> no zeroing kernel.
__device__ float    g_part[GRID1 * 128];
// Per-batch M[a][n], produced by each batch's last-arriving k1 block.
__device__ float    g_M[NB * 128];
// Per-vertex edge weights exported by k1 (8 floats, 32B aligned).
__device__ float    g_ew[(size_t)NB * NV * NA];
// Monotonic per-batch arrival counters (replay-safe: act on (old&15)==15).
__device__ unsigned g_cnt[NB];

// ---------------------------------------------------------------------------
// k1: per-warp staged aggregation (1 block barrier total) + ew export +
//     per-batch fan-in -> g_M.
// ---------------------------------------------------------------------------
__global__ __launch_bounds__(256, 4) void k_aggregate(
    const float* __restrict__ data, const int* __restrict__ num_vertex,
    const float* __restrict__ W_flr, const float* __restrict__ b_flr,
    const float* __restrict__ W_s,   const float* __restrict__ b_s,
    const float* __restrict__ W_out)
{
    __shared__ float4 sWf4[NFEAT][4];
    __shared__ float4 sWs4[NFEAT][2];
    __shared__ float  sbf[NP];
    __shared__ float  sbs[NA];
    __shared__ float4 sStage[CH * 6];    // [0..3]=feat, [4..5]=ew; 24KB
    __shared__ float4 sRed[256];         // separate -> no aliasing with sStage
    __shared__ float  sFan[128];
    __shared__ unsigned sLast;

    const int t     = threadIdx.x;
    const int lane  = t & 31;
    const int w     = t >> 5;
    const int b     = blockIdx.x / S1;
    const int split = blockIdx.x % S1;
    const int nv    = num_vertex[b];
    const int vbase = split * CH;
    const bool work = (vbase < nv);       // block-uniform
    const float4 z  = make_float4(0.f, 0.f, 0.f, 0.f);

    if (work) {
        if (t < 64) {
            sWf4[t >> 2][t & 3] = ((const float4*)W_flr)[t];
        } else if (t < 96) {
            const int u = t - 64;
            sWs4[u >> 1][u & 1] = ((const float4*)W_s)[u];
        } else if (t < 112) {
            sbf[t - 96] = b_flr[t - 96];
        } else if (t < 120) {
            sbs[t - 112] = b_s[t - 112];
        }
        __syncthreads();                  // weights ready (barrier 1 of 2)

        const int v = vbase + t;
        if (v < nv) {
            const float4* dp = (const float4*)(data + ((size_t)(b * NV + v)) * NFEAT);
            const float4 x0 = dp[0], x1 = dp[1], x2 = dp[2], x3 = dp[3];
            float x[16];
            x[0]=x0.x;  x[1]=x0.y;  x[2]=x0.z;  x[3]=x0.w;
            x[4]=x1.x;  x[5]=x1.y;  x[6]=x1.z;  x[7]=x1.w;
            x[8]=x2.x;  x[9]=x2.y;  x[10]=x2.z; x[11]=x2.w;
            x[12]=x3.x; x[13]=x3.y; x[14]=x3.z; x[15]=x3.w;

            #pragma unroll
            for (int g = 0; g < 4; ++g) {
                float s0 = sbf[g*4+0], s1 = sbf[g*4+1];
                float s2 = sbf[g*4+2], s3 = sbf[g*4+3];
                #pragma unroll
                for (int f = 0; f < 16; ++f) {
                    const float4 wv = sWf4[f][g];
                    s0 += x[f]*wv.x; s1 += x[f]*wv.y;
                    s2 += x[f]*wv.z; s3 += x[f]*wv.w;
                }
                sStage[t*6 + g] = make_float4(s0, s1, s2, s3);
            }
            {
                float s0 = sbs[0], s1 = sbs[1], s2 = sbs[2], s3 = sbs[3];
                float u0 = sbs[4], u1 = sbs[5], u2 = sbs[6], u3 = sbs[7];
                #pragma unroll
                for (int f = 0; f < 16; ++f) {
                    const float4 w0 = sWs4[f][0];
                    const float4 w1 = sWs4[f][1];
                    s0 += x[f]*w0.x; s1 += x[f]*w0.y;
                    s2 += x[f]*w0.z; s3 += x[f]*w0.w;
                    u0 += x[f]*w1.x; u1 += x[f]*w1.y;
                    u2 += x[f]*w1.z; u3 += x[f]*w1.w;
                }
                const float4 e0 = make_float4(__expf(-s0*s0), __expf(-s1*s1),
                                              __expf(-s2*s2), __expf(-s3*s3));
                const float4 e1 = make_float4(__expf(-u0*u0), __expf(-u1*u1),
                                              __expf(-u2*u2), __expf(-u3*u3));
                sStage[t*6 + 4] = e0;
                sStage[t*6 + 5] = e1;
                float4* ewp = (float4*)(g_ew + ((size_t)(b * NV + v)) * NA);
                ewp[0] = e0; ewp[1] = e1;          // export (coalesced 32B)
            }
        } else {
            #pragma unroll
            for (int g = 0; g < 6; ++g) sStage[t*6 + g] = z;
        }
        __syncwarp();                      // warp's own rows staged

        // Per-warp reduce over OWN 32 rows. lane -> pair group (aa=l>>2, pg=l&3).
        const int aa = lane >> 2;
        const int pg = lane & 3;
        const float* sS = (const float*)sStage;
        float4 acc = z;
        if (vbase + w * 32 < nv) {         // warp-uniform dead-slice skip
            const int r0 = w * 32;
            #pragma unroll 8
            for (int i = 0; i < 32; ++i) {
                const int vv = r0 + i;
                const float  ww = sS[vv*24 + 16 + aa];   // broadcast scalar
                const float4 ff = sStage[vv*6 + pg];     // 4-way multicast
                acc.x += ww * ff.x; acc.y += ww * ff.y;
                acc.z += ww * ff.z; acc.w += ww * ff.w;
            }
        }
        sRed[w * 32 + lane] = acc;         // separate buffer: no race with stage
        __syncthreads();                   // barrier 2 of 2

        if (t < 32) {
            float4 s = sRed[t];
            #pragma unroll
            for (int sl = 1; sl < 8; ++sl) {
                const float4 r = sRed[sl * 32 + t];
                s.x += r.x; s.y += r.y; s.z += r.z; s.w += r.w;
            }
            ((float4*)g_part)[blockIdx.x * 32 + t] = s;
            __threadfence();               // release partial
        }
    } else {
        if (t < 32) {
            ((float4*)g_part)[blockIdx.x * 32 + t] = z;
            __threadfence();
        }
    }
    __syncthreads();                       // all partials fenced before arrival

    // ---- per-batch fan-in: last arrival reduces partials, computes M ----
    if (t == 0) {
        const unsigned old = atomicAdd(&g_cnt[b], 1u);
        sLast = ((old & (S1 - 1)) == (S1 - 1)) ? 1u : 0u;
    }
    __syncthreads();
    if (sLast) {
        __threadfence();                   // acquire siblings' partials
        if (t < 32) {
            float4 s = z;
            #pragma unroll
            for (int sp = 0; sp < S1; ++sp) {
                const float4 r = ((const float4*)g_part)[(b * S1 + sp) * 32 + t];
                s.x += r.x; s.y += r.y; s.z += r.z; s.w += r.w;
            }
            const float inv = 1.0f / (float)NV;
            s.x *= inv; s.y *= inv; s.z *= inv; s.w *= inv;
            ((float4*)sFan)[t] = s;        // agg[a*16+p]
        }
        __syncthreads();
        if (t < 128) {
            const int a = t >> 4, n = t & 15;
            float m = 0.f;
            #pragma unroll
            for (int p = 0; p < NP; ++p)
                m += sFan[a*NP + p] * W_out[(a*NP + p)*NOUT + n];
            g_M[b * 128 + t] = m;          // visible to k2 via launch edge
        }
    }
}

// ---------------------------------------------------------------------------
// k2: featherweight epilogue. out[b,v,:] = mask*(sum_a ew[v,a]*M[b,a,:]+b_out)
//     ~42 regs -> 6 blocks/SM -> ~75% occupancy.
// ---------------------------------------------------------------------------
__global__ __launch_bounds__(256, 6) void k_output(
    const int* __restrict__ num_vertex, const float* __restrict__ b_out,
    float* __restrict__ out)
{
    __shared__ __align__(16) float sM[128];
    __shared__ float sbo[NOUT];

    const int t  = threadIdx.x;
    const int b  = blockIdx.x / S1;
    const int vb = (blockIdx.x % S1) * CH;
    const int nv = num_vertex[b];
    const int v  = vb + t;
    float4* op = (float4*)(out + ((size_t)(b * NV + v)) * NOUT);
    const float4 z = make_float4(0.f, 0.f, 0.f, 0.f);

    if (vb >= nv) {                        // fully masked block: zeros
        op[0] = z; op[1] = z; op[2] = z; op[3] = z;
        return;
    }

    // Hoist ew loads (L2-hot from k1) to overlap the smem prologue.
    const bool valid = (v < nv);
    float4 e0 = z, e1 = z;
    if (valid) {
        const float4* ep = (const float4*)(g_ew + ((size_t)(b * NV + v)) * NA);
        e0 = ep[0]; e1 = ep[1];
    }

    if (t < 32) {
        ((float4*)sM)[t] = ((const float4*)g_M)[b * 32 + t];
    } else if (t < 48) {
        sbo[t - 32] = b_out[t - 32];
    }
    __syncthreads();

    if (valid) {
        const float ew[8] = {e0.x, e0.y, e0.z, e0.w, e1.x, e1.y, e1.z, e1.w};
        float4 o[4];
        #pragma unroll
        for (int j = 0; j < 4; ++j)
            o[j] = make_float4(sbo[j*4], sbo[j*4+1], sbo[j*4+2], sbo[j*4+3]);
        #pragma unroll
        for (int a = 0; a < NA; ++a) {
            const float wv = ew[a];
            const float4* mrow = (const float4*)(sM + a * NOUT);
            #pragma unroll
            for (int j = 0; j < 4; ++j) {
                const float4 m = mrow[j];  // uniform address -> broadcast LDS
                o[j].x += wv * m.x; o[j].y += wv * m.y;
                o[j].z += wv * m.z; o[j].w += wv * m.w;
            }
        }
        op[0] = o[0]; op[1] = o[1]; op[2] = o[2]; op[3] = o[3];
    } else {
        op[0] = z; op[1] = z; op[2] = z; op[3] = z;
    }
}

extern "C" void kernel_launch(void* const* d_in, const int* in_sizes, int n_in,
                              void* d_out, int out_size) {
    const float* data       = (const float*)d_in[0];
    const int*   num_vertex = (const int*)  d_in[1];
    const float* W_flr      = (const float*)d_in[2];
    const float* b_flr      = (const float*)d_in[3];
    const float* W_s        = (const float*)d_in[4];
    const float* b_s        = (const float*)d_in[5];
    const float* W_out      = (const float*)d_in[6];
    const float* b_out      = (const float*)d_in[7];
    float* out = (float*)d_out;

    k_aggregate<<<GRID1, 256>>>(data, num_vertex, W_flr, b_flr, W_s, b_s, W_out);
    k_output<<<GRID1, 256>>>(num_vertex, b_out, out);
}